// round 12
// baseline (speedup 1.0000x reference)
#include <cuda_runtime.h>
#include <cuda_fp16.h>

#define BB   2
#define SS   2048
#define HIDD 1024
#define NH   16
#define NKV  4
#define HD   64
#define SCL2 0.1803368801f // (1/sqrt(64)) * log2(e); folded into Q at write time

// Scratch (static device globals — allocation-free), all fp16.
// k-interleaved within each 16-block: k -> ((k&7)>>1)*4 + (k&1) + ((k>>3)&1)*2
// g_Q (pre-scaled by SCL2), g_K: [b][h][s][d] (d interleaved).
// g_V: [b][hkv][d][s] (s interleaved). g_CTX: [b][s][h*d] (d interleaved).
__device__ __half g_Q[BB*NH*SS*HD];
__device__ __half g_K[BB*NKV*SS*HD];
__device__ __half g_V[BB*NKV*HD*SS];
__device__ __half g_CTX[BB*SS*NH*HD];
__device__ __half g_Xt[BB*SS*HIDD];
__device__ __half g_Wt[1536*HIDD];
__device__ __half g_Wot[HIDD*HIDD];

// ---------------------------------------------------------------------------
// helpers
// ---------------------------------------------------------------------------
__device__ __forceinline__ int perm16(int l) {      // interleave within 16-block
    return ((l & 7) >> 1) * 4 + (l & 1) + ((l >> 3) & 1) * 2;
}
__device__ __forceinline__ int kp16(int k) { return (k & ~15) | perm16(k & 15); }

__device__ __forceinline__ unsigned packh2(float a, float b) {
    __half2 h = __floats2half2_rn(a, b);
    return *(unsigned*)&h;
}

__device__ __forceinline__ void mma16(float* c, unsigned a0, unsigned a1,
                                      unsigned a2, unsigned a3,
                                      unsigned b0, unsigned b1) {
    asm volatile(
        "mma.sync.aligned.m16n8k16.row.col.f32.f16.f16.f32 "
        "{%0,%1,%2,%3},{%4,%5,%6,%7},{%8,%9},{%0,%1,%2,%3};"
        : "+f"(c[0]), "+f"(c[1]), "+f"(c[2]), "+f"(c[3])
        : "r"(a0), "r"(a1), "r"(a2), "r"(a3), "r"(b0), "r"(b1));
}

__device__ __forceinline__ void cp16(void* dst, const void* src) {
    unsigned d = (unsigned)__cvta_generic_to_shared(dst);
    asm volatile("cp.async.cg.shared.global [%0], [%1], 16;\n" :: "r"(d), "l"(src));
}
__device__ __forceinline__ void cpcommit() { asm volatile("cp.async.commit_group;\n"); }
__device__ __forceinline__ void cpwait0()  { asm volatile("cp.async.wait_group 0;\n" ::: "memory"); }

// ---------------------------------------------------------------------------
// Kernel 0: f32 -> f16 with 16-block k-interleave for X / Wq / Wk / Wv / Wo
// {0,1,8,9, 2,3,10,11, 4,5,12,13, 6,7,14,15}
// ---------------------------------------------------------------------------
__global__ __launch_bounds__(256) void cvt_kernel(
    const float* __restrict__ X,  const float* __restrict__ Wq,
    const float* __restrict__ Wk, const float* __restrict__ Wv,
    const float* __restrict__ Wo)
{
    long i = (long)blockIdx.x * 256 + threadIdx.x;   // 16-float group index
    const float* s; __half* d;
    if (i < 262144L)      { s = X  + i*16;               d = g_Xt  + i*16; }
    else if (i < 327680L) { long j = i - 262144L; s = Wq + j*16; d = g_Wt + j*16; }
    else if (i < 344064L) { long j = i - 327680L; s = Wk + j*16; d = g_Wt + 1048576L + j*16; }
    else if (i < 360448L) { long j = i - 344064L; s = Wv + j*16; d = g_Wt + 1310720L + j*16; }
    else                  { long j = i - 360448L; s = Wo + j*16; d = g_Wot + j*16; }
    float4 f0 = ((const float4*)s)[0];
    float4 f1 = ((const float4*)s)[1];
    float4 f2 = ((const float4*)s)[2];
    float4 f3 = ((const float4*)s)[3];
    uint4 o0, o1;
    o0.x = packh2(f0.x, f0.y); o0.y = packh2(f2.x, f2.y);
    o0.z = packh2(f0.z, f0.w); o0.w = packh2(f2.z, f2.w);
    o1.x = packh2(f1.x, f1.y); o1.y = packh2(f3.x, f3.y);
    o1.z = packh2(f1.z, f1.w); o1.w = packh2(f3.z, f3.w);
    ((uint4*)d)[0] = o0;
    ((uint4*)d)[1] = o1;
}

// ---------------------------------------------------------------------------
// GEMM core: block 128x128, BK=64 halves, 256 threads = 8 warps (2m x 4n),
// warp tile 64x32, fp16 m16n8k16.  Row stride 160 B; conflict-free LDS.64.
// 2-stage cp.async, 1 barrier per k-iter.
// ---------------------------------------------------------------------------
#define GROWB 160                       // bytes per smem row
#define GEMM_STAGE_B (2*128*GROWB)      // 40960 B per stage (A+B)

__device__ __forceinline__ void gemm_stage(char* smc, int s, int k0,
                                           const __half* A, const __half* B, int tid)
{
    char* As = smc + s*GEMM_STAGE_B;
    char* Bs = As + 128*GROWB;
    #pragma unroll
    for (int q = 0; q < 4; q++) {
        int e = q*256 + tid; int r = e >> 3, c = e & 7;
        cp16(As + r*GROWB + c*16, A + (long)r*HIDD + k0 + c*8);
    }
    #pragma unroll
    for (int q = 0; q < 4; q++) {
        int e = q*256 + tid; int r = e >> 3, c = e & 7;
        cp16(Bs + r*GROWB + c*16, B + (long)r*HIDD + k0 + c*8);
    }
    cpcommit();
}

__device__ __forceinline__ void gemm_body(char* smc, const __half* A, const __half* B,
                                          float acc[4][4][4], int tid)
{
    const int lane = tid & 31, w = tid >> 5;
    const int g = lane >> 2, t = lane & 3;
    const int wm = (w >> 2) << 6;     // 0 or 64
    const int wn = (w & 3) << 5;      // 0,32,64,96

    gemm_stage(smc, 0, 0, A, B, tid);

    for (int kt = 0; kt < 16; kt++) {
        const int s = kt & 1;
        cpwait0();
        __syncthreads();
        if (kt + 1 < 16) gemm_stage(smc, s ^ 1, (kt + 1) << 6, A, B, tid);
        const char* As = smc + s*GEMM_STAGE_B;
        const char* Bs = As + 128*GROWB;
        #pragma unroll
        for (int ks = 0; ks < 4; ks++) {
            const int kb = ks*32 + t*8;
            unsigned a[4][4]; uint2 b[4];
            #pragma unroll
            for (int i = 0; i < 4; i++) {
                uint2 lo = *(const uint2*)(As + (wm + i*16 + g)*GROWB + kb);
                uint2 hi = *(const uint2*)(As + (wm + i*16 + g + 8)*GROWB + kb);
                a[i][0] = lo.x; a[i][2] = lo.y;
                a[i][1] = hi.x; a[i][3] = hi.y;
            }
            #pragma unroll
            for (int j = 0; j < 4; j++)
                b[j] = *(const uint2*)(Bs + (wn + j*8 + g)*GROWB + kb);
            #pragma unroll
            for (int i = 0; i < 4; i++)
                #pragma unroll
                for (int j = 0; j < 4; j++)
                    mma16(acc[i][j], a[i][0], a[i][1], a[i][2], a[i][3],
                          b[j].x, b[j].y);
        }
    }
}

// ---------------------------------------------------------------------------
// Kernel 1: QKV GEMM + per-head RMSNorm + RoPE epilogue (Q scaled by SCL2)
// ---------------------------------------------------------------------------
__global__ __launch_bounds__(256, 2) void qkv_kernel(
    const float* __restrict__ cosT, const float* __restrict__ sinT,
    const int*   __restrict__ pos,
    const float* __restrict__ qw, const float* __restrict__ kw)
{
    extern __shared__ __align__(16) char smc[];
    const int tid  = threadIdx.x;
    const int lane = tid & 31, w = tid >> 5;
    const int g = lane >> 2, t = lane & 3;
    const int wm = (w >> 2) << 6;
    const int wn = (w & 3) << 5;
    const int m0 = blockIdx.y << 7;
    const int n0 = blockIdx.x << 7;

    const __half* A = g_Xt + (long)m0*HIDD;
    const __half* B = g_Wt + (long)n0*HIDD;

    float acc[4][4][4];
    #pragma unroll
    for (int i = 0; i < 4; i++)
        #pragma unroll
        for (int j = 0; j < 4; j++)
            #pragma unroll
            for (int e = 0; e < 4; e++) acc[i][j][e] = 0.f;

    gemm_body(smc, A, B, acc, tid);

    // stage C (f32) to smem stride 129 for row-wise epilogue
    __syncthreads();
    float* Cs = (float*)smc;
    #pragma unroll
    for (int i = 0; i < 4; i++)
        #pragma unroll
        for (int j = 0; j < 4; j++) {
            int r = wm + i*16 + g;
            int c = wn + j*8 + 2*t;
            Cs[r*129 + c]         = acc[i][j][0];
            Cs[r*129 + c + 1]     = acc[i][j][1];
            Cs[(r+8)*129 + c]     = acc[i][j][2];
            Cs[(r+8)*129 + c + 1] = acc[i][j][3];
        }
    __syncthreads();

    {
        const int r    = tid & 127;
        const int seg  = tid >> 7;          // 0/1: which 64-col head segment
        const int n    = n0 + (seg << 6);
        int mode, h;
        if (n < 1024)      { mode = 0; h = n >> 6; }
        else if (n < 1280) { mode = 1; h = (n-1024) >> 6; }
        else               { mode = 2; h = (n-1280) >> 6; }

        const int mrow = m0 + r;
        const int b    = mrow >> 11;
        const int srow = mrow & 2047;
        float* Crow = &Cs[r*129 + (seg << 6)];
        if (mode == 2) {
            // V: [b][hkv][d][s], kv(s) interleaved
            __half* dst = g_V + ((long)(b*NKV + h)*HD)*SS + kp16(srow);
            #pragma unroll
            for (int d = 0; d < 64; d++) dst[(long)d*SS] = __float2half_rn(Crow[d]);
        } else {
            float ssum = 0.f;
            #pragma unroll
            for (int d = 0; d < 64; d++) { float v = Crow[d]; ssum = fmaf(v, v, ssum); }
            const float rstd = rsqrtf(ssum * (1.f/64.f) + 1e-6f);
            const float* wn2 = (mode == 0) ? qw : kw;
            const float qsc  = (mode == 0) ? SCL2 : 1.f;   // fold score scale into Q
            #pragma unroll
            for (int d = 0; d < 64; d++) Crow[d] = Crow[d] * rstd * wn2[d];
            const int p = pos[b*SS + srow];
            const float* cr = cosT + (p << 6);
            const float* sr = sinT + (p << 6);
            __half* dst = (mode == 0) ? (g_Q + (((long)(b*NH  + h)*SS + srow) << 6))
                                      : (g_K + (((long)(b*NKV + h)*SS + srow) << 6));
            #pragma unroll
            for (int d = 0; d < 32; d++) {                  // d interleaved
                float x1 = Crow[d], x2 = Crow[d+32];
                dst[kp16(d)]      = __float2half_rn((x1*cr[d]    - x2*sr[d])    * qsc);
                dst[kp16(d + 32)] = __float2half_rn((x2*cr[d+32] + x1*sr[d+32]) * qsc);
            }
        }
    }
}

// ---------------------------------------------------------------------------
// Kernel 2: causal flash attention, fp16 MMA.
// q-tile 64 rows, 4 warps.  FUSED per-chunk dataflow: for each 16-col kv
// chunk, QK mma (8) -> exp/mask -> pack A-frags (4 regs) -> PV mma (9).
// Peak live registers ~85 (was ~130 with full sacc/ph arrays -> spills);
// MUFU interleaves with HMMA.  smem 43.5 KB + low regs -> up to 5 blocks/SM.
// Unbiased fixed-scale softmax (Q carries SCL2); row sums via V ones-column.
// ---------------------------------------------------------------------------
#define AROWB 160
#define KTILB (64*AROWB)        // 10240 B
#define VTILB (72*AROWB)        // 11520 B
__global__ __launch_bounds__(128, 4) void attn_kernel()
{
    extern __shared__ __align__(16) char smc[];
    char* Kb = smc;                      // [2][KTILB]
    char* Vb = smc + 2*KTILB;            // [2][VTILB]

    const int tid  = threadIdx.x;
    const int lane = tid & 31;
    const int w    = tid >> 5;           // 0..3
    const int g = lane >> 2, t = lane & 3;
    const int qt = gridDim.x - 1 - blockIdx.x;   // heavy tiles first
    const int h = blockIdx.y, b = blockIdx.z;
    const int q0  = qt << 6;
    const int hkv = h >> 2;

    const __half* Qg = g_Q + (((long)(b*NH  + h  )*SS + q0 + w*16) << 6);
    const __half* Kg = g_K + (( (long)(b*NKV + hkv)*SS)             << 6);
    const __half* Vg = g_V + (  (long)(b*NKV + hkv)*HD)*SS;

    // static V extension rows (d = 64..71 in each buffer): row 64 = 1.0
    for (int i = tid; i < 2*8*40; i += 128) {
        int buf = i / 320, rem = i % 320;
        int row = 64 + rem / 40, c = rem % 40;
        ((unsigned*)(Vb + buf*VTILB + row*AROWB))[c] = (row == 64) ? 0x3C003C00u : 0u;
    }

    // preload Q fragments (d interleaved -> uint2 loads)
    unsigned aq[4][4];
    #pragma unroll
    for (int ks = 0; ks < 4; ks++) {
        uint2 lo = *(const uint2*)((const char*)Qg + ( g     *64)*2 + ks*32 + t*8);
        uint2 hi = *(const uint2*)((const char*)Qg + ((g + 8)*64)*2 + ks*32 + t*8);
        aq[ks][0] = lo.x; aq[ks][2] = lo.y;
        aq[ks][1] = hi.x; aq[ks][3] = hi.y;
    }

    float oacc[9][4];                    // [8] = row-sum column (l)
    #pragma unroll
    for (int j = 0; j < 9; j++)
        #pragma unroll
        for (int e = 0; e < 4; e++) oacc[j][e] = 0.f;

    const int nkt = qt + 1;

    {   // prologue: stage tile 0 into buf 0
        #pragma unroll
        for (int q = 0; q < 4; q++) {
            int e = q*128 + tid; int r = e >> 3, c = e & 7;
            cp16(Kb + r*AROWB + c*16, Kg + r*64 + c*8);
            cp16(Vb + r*AROWB + c*16, Vg + (long)r*SS + c*8);
        }
        cpcommit();
    }

    for (int kt = 0; kt < nkt; kt++) {
        const int s = kt & 1;
        cpwait0();
        __syncthreads();
        if (kt + 1 < nkt) {
            const __half* Kt = Kg + (kt+1)*4096;
            const __half* Vt = Vg + (kt+1)*64;
            char* Kd = Kb + (s^1)*KTILB;
            char* Vd = Vb + (s^1)*VTILB;
            #pragma unroll
            for (int q = 0; q < 4; q++) {
                int e = q*128 + tid; int r = e >> 3, c = e & 7;
                cp16(Kd + r*AROWB + c*16, Kt + r*64 + c*8);
                cp16(Vd + r*AROWB + c*16, Vt + (long)r*SS + c*8);
            }
            cpcommit();
        }

        const char* Kc = Kb + s*KTILB;
        const char* Vc = Vb + s*VTILB;
        const bool diag = (kt == qt);

        // fused S->exp->PV per 16-column kv chunk (j0 = 2ks, j1 = 2ks+1)
        #pragma unroll
        for (int ks = 0; ks < 4; ks++) {
            float s0[4] = {0.f, 0.f, 0.f, 0.f};
            float s1[4] = {0.f, 0.f, 0.f, 0.f};
            #pragma unroll
            for (int kq = 0; kq < 4; kq++) {
                uint2 b0 = *(const uint2*)(Kc + ((2*ks  )*8 + g)*AROWB + kq*32 + t*8);
                uint2 b1 = *(const uint2*)(Kc + ((2*ks+1)*8 + g)*AROWB + kq*32 + t*8);
                mma16(s0, aq[kq][0], aq[kq][1], aq[kq][2], aq[kq][3], b0.x, b0.y);
                mma16(s1, aq[kq][0], aq[kq][1], aq[kq][2], aq[kq][3], b1.x, b1.y);
            }

            float p00 = exp2f(s0[0]), p01 = exp2f(s0[1]);
            float p02 = exp2f(s0[2]), p03 = exp2f(s0[3]);
            float p10 = exp2f(s1[0]), p11 = exp2f(s1[1]);
            float p12 = exp2f(s1[2]), p13 = exp2f(s1[3]);
            if (diag) {
                int c0  = (kt << 6) + (2*ks)*8 + 2*t;
                int c1  = c0 + 8;
                int rlo = q0 + w*16 + g;
                int rhi = rlo + 8;
                if (c0     > rlo) p00 = 0.f;
                if (c0 + 1 > rlo) p01 = 0.f;
                if (c0     > rhi) p02 = 0.f;
                if (c0 + 1 > rhi) p03 = 0.f;
                if (c1     > rlo) p10 = 0.f;
                if (c1 + 1 > rlo) p11 = 0.f;
                if (c1     > rhi) p12 = 0.f;
                if (c1 + 1 > rhi) p13 = 0.f;
            }
            unsigned a0 = packh2(p00, p01);   // rows g,    cols j0
            unsigned a1 = packh2(p02, p03);   // rows g+8,  cols j0
            unsigned a2 = packh2(p10, p11);   // rows g,    cols j1
            unsigned a3 = packh2(p12, p13);   // rows g+8,  cols j1

            // O += P V for this kv chunk (j=8 accumulates row sums)
            #pragma unroll
            for (int j = 0; j < 9; j++) {
                uint2 bv = *(const uint2*)(Vc + (j*8 + g)*AROWB + ks*32 + t*8);
                mma16(oacc[j], a0, a1, a2, a3, bv.x, bv.y);
            }
        }
    }

    // l lives in oacc[8][0] (row g) / oacc[8][2] (row g+8) of t=0 lanes
    const float l_lo = __shfl_sync(0xffffffffu, oacc[8][0], lane & ~3);
    const float l_hi = __shfl_sync(0xffffffffu, oacc[8][2], lane & ~3);
    const float inv_lo = 1.f / l_lo, inv_hi = 1.f / l_hi;

    // epilogue: CTX fp16, d interleaved (consumed by out_kernel GEMM)
    __half* Cg = g_CTX + ((long)(b*SS + q0 + w*16) << 10) + (h << 6);
    #pragma unroll
    for (int j = 0; j < 8; j++) {
        int cpos = (j >> 1)*16 + 4*t + 2*(j & 1);     // half index within head
        *(unsigned*)((char*)Cg + ( g     *1024)*2 + cpos*2) =
            packh2(oacc[j][0]*inv_lo, oacc[j][1]*inv_lo);
        *(unsigned*)((char*)Cg + ((g + 8)*1024)*2 + cpos*2) =
            packh2(oacc[j][2]*inv_hi, oacc[j][3]*inv_hi);
    }
}

// ---------------------------------------------------------------------------
// Kernel 3: output projection, direct fragment stores
// ---------------------------------------------------------------------------
__global__ __launch_bounds__(256, 2) void out_kernel(float* __restrict__ out)
{
    extern __shared__ __align__(16) char smc[];
    const int tid  = threadIdx.x;
    const int lane = tid & 31, w = tid >> 5;
    const int g = lane >> 2, t = lane & 3;
    const int wm = (w >> 2) << 6;
    const int wn = (w & 3) << 5;
    const int m0 = blockIdx.y << 7;
    const int n0 = blockIdx.x << 7;

    const __half* A = g_CTX + (long)m0*HIDD;
    const __half* B = g_Wot + (long)n0*HIDD;

    float acc[4][4][4];
    #pragma unroll
    for (int i = 0; i < 4; i++)
        #pragma unroll
        for (int j = 0; j < 4; j++)
            #pragma unroll
            for (int e = 0; e < 4; e++) acc[i][j][e] = 0.f;

    gemm_body(smc, A, B, acc, tid);

    #pragma unroll
    for (int i = 0; i < 4; i++)
        #pragma unroll
        for (int j = 0; j < 4; j++) {
            int r = m0 + wm + i*16 + g;
            int c = n0 + wn + j*8 + 2*t;
            float2 v0 = { acc[i][j][0], acc[i][j][1] };
            *(float2*)&out[(long)r*1024 + c] = v0;
            float2 v1 = { acc[i][j][2], acc[i][j][3] };
            *(float2*)&out[(long)(r+8)*1024 + c] = v1;
        }
}

// ---------------------------------------------------------------------------
extern "C" void kernel_launch(void* const* d_in, const int* in_sizes, int n_in,
                              void* d_out, int out_size)
{
    const float* X    = (const float*)d_in[0];
    const float* cosT = (const float*)d_in[1];
    const float* sinT = (const float*)d_in[2];
    const int*   pos  = (const int*)  d_in[3];
    // d_in[4] = attention_mask (causal; applied analytically)
    const float* Wq   = (const float*)d_in[5];
    const float* Wk   = (const float*)d_in[6];
    const float* Wv   = (const float*)d_in[7];
    const float* Wo   = (const float*)d_in[8];
    const float* qw   = (const float*)d_in[9];
    const float* kw   = (const float*)d_in[10];
    float* out = (float*)d_out;

    const int gemm_smem = 2*GEMM_STAGE_B;            // 81920 B
    const int attn_smem = 2*KTILB + 2*VTILB;         // 43520 B
    cudaFuncSetAttribute(qkv_kernel, cudaFuncAttributeMaxDynamicSharedMemorySize, gemm_smem);
    cudaFuncSetAttribute(out_kernel, cudaFuncAttributeMaxDynamicSharedMemorySize, gemm_smem);
    cudaFuncSetAttribute(attn_kernel, cudaFuncAttributeMaxDynamicSharedMemorySize, attn_smem);

    cvt_kernel<<<1664, 256>>>(X, Wq, Wk, Wv, Wo);
    qkv_kernel<<<dim3(12, 32), 256, gemm_smem>>>(cosT, sinT, pos, qw, kw);
    attn_kernel<<<dim3(SS/64, NH, BB), 128, attn_smem>>>();
    out_kernel<<<dim3(8, 32), 256, gemm_smem>>>(out);
}